// round 5
// baseline (speedup 1.0000x reference)
#include <cuda_runtime.h>
#include <math.h>

#define H 256
#define T 512
#define B 64
#define M_TOT (B*T)   // 32768

// ---------------- scratch (static device globals; no allocation) ----------------
__device__ float d_Wfq[H*H];            // W1[3H:4H] + W1[4H:5H]
__device__ float d_Wabs[H*H];           // W1[5H:6H] + W1[6H:7H]
__device__ float d_attpre[B*H];         // q@(W1[H:2H]+W1[2H:3H]) + b1
__device__ float d_ms[B];               // q . Ws[0:H]
__device__ float d_me[B];               // q . We[0:H]
__device__ float d_V[M_TOT*H];          // tanh(feats@W1 + b1)
__device__ float d_att[M_TOT];          // logits
__device__ float d_g[M_TOT];            // softmax gates
__device__ float d_xrh[(size_t)M_TOT*2*H]; // [m][0:256]=x@Wr+br, [256:512]=x@Wh+bh

// ---------------- K0: combine W1 slices ----------------
__global__ __launch_bounds__(256) void prep_w_kernel(const float* __restrict__ W1)
{
    int i = blockIdx.x * 256 + threadIdx.x;           // 65536 total
    d_Wfq[i]  = W1[196608 + i] + W1[262144 + i];      // rows [3H,4H) + [4H,5H)
    d_Wabs[i] = W1[327680 + i] + W1[393216 + i];      // rows [5H,6H) + [6H,7H)
}

// ---------------- K1: per-batch precompute ----------------
__global__ __launch_bounds__(256) void prep_batch_kernel(
    const float* __restrict__ qv, const float* __restrict__ W1,
    const float* __restrict__ b1, const float* __restrict__ Ws,
    const float* __restrict__ We)
{
    const int b = blockIdx.x, j = threadIdx.x;
    __shared__ float qs[H];
    __shared__ float redS[8], redE[8];
    qs[j] = qv[b*H + j];
    __syncthreads();

    float acc = 0.f;
#pragma unroll 8
    for (int k = 0; k < H; ++k)
        acc += qs[k] * (W1[(H + k)*H + j] + W1[(2*H + k)*H + j]);
    d_attpre[b*H + j] = acc + b1[j];

    float ps = qs[j] * Ws[j];
    float pe = qs[j] * We[j];
#pragma unroll
    for (int off = 16; off; off >>= 1) {
        ps += __shfl_xor_sync(0xffffffffu, ps, off);
        pe += __shfl_xor_sync(0xffffffffu, pe, off);
    }
    if ((j & 31) == 0) { redS[j >> 5] = ps; redE[j >> 5] = pe; }
    __syncthreads();
    if (j == 0) {
        float s = 0.f, se = 0.f;
#pragma unroll
        for (int w = 0; w < 8; ++w) { s += redS[w]; se += redE[w]; }
        d_ms[b] = s;
        d_me[b] = se;
    }
}

// ---------------- K2a: attention GEMM (M=32768, K=768 virtual, N=256) ----------------
// C = tanh(acc + attpre[b]) -> d_V
__global__ __launch_bounds__(256) void gemm_att_kernel(
    const float* __restrict__ fact, const float* __restrict__ qv,
    const float* __restrict__ W1)
{
    __shared__ float As[16][64];
    __shared__ float Bs[16][64];
    const int tid = threadIdx.x;
    const int m0 = blockIdx.x * 64;        // 64 consecutive rows: same batch (512/64=8)
    const int n0 = blockIdx.y * 64;
    const int b  = m0 >> 9;
    const int tx = tid & 15, ty = tid >> 4;
    const int arow = tid >> 2, akq = (tid & 3) * 4;
    const int bkr = tid >> 4,  bjc = (tid & 15) * 4;

    float acc[4][4] = {};

    for (int sel = 0; sel < 3; ++sel) {
        const float* __restrict__ W = (sel == 0) ? W1 : (sel == 1) ? d_Wfq : d_Wabs;
        for (int kp0 = 0; kp0 < H; kp0 += 16) {
            // A tile on the fly
            float4 f4 = *(const float4*)(fact + (m0 + arow)*H + kp0 + akq);
            float4 q4 = *(const float4*)(qv + b*H + kp0 + akq);
            float4 v4;
            if (sel == 0)      v4 = f4;
            else if (sel == 1) { v4.x = f4.x*q4.x; v4.y = f4.y*q4.y;
                                 v4.z = f4.z*q4.z; v4.w = f4.w*q4.w; }
            else               { v4.x = fabsf(f4.x - q4.x); v4.y = fabsf(f4.y - q4.y);
                                 v4.z = fabsf(f4.z - q4.z); v4.w = fabsf(f4.w - q4.w); }
            As[akq + 0][arow] = v4.x;
            As[akq + 1][arow] = v4.y;
            As[akq + 2][arow] = v4.z;
            As[akq + 3][arow] = v4.w;
            *(float4*)&Bs[bkr][bjc] = *(const float4*)(W + (kp0 + bkr)*H + n0 + bjc);
            __syncthreads();
#pragma unroll
            for (int k = 0; k < 16; ++k) {
                float4 a  = *(const float4*)&As[k][ty * 4];
                float4 bb = *(const float4*)&Bs[k][tx * 4];
                acc[0][0] += a.x*bb.x; acc[0][1] += a.x*bb.y; acc[0][2] += a.x*bb.z; acc[0][3] += a.x*bb.w;
                acc[1][0] += a.y*bb.x; acc[1][1] += a.y*bb.y; acc[1][2] += a.y*bb.z; acc[1][3] += a.y*bb.w;
                acc[2][0] += a.z*bb.x; acc[2][1] += a.z*bb.y; acc[2][2] += a.z*bb.z; acc[2][3] += a.z*bb.w;
                acc[3][0] += a.w*bb.x; acc[3][1] += a.w*bb.y; acc[3][2] += a.w*bb.z; acc[3][3] += a.w*bb.w;
            }
            __syncthreads();
        }
    }
#pragma unroll
    for (int i = 0; i < 4; ++i) {
        int m = m0 + ty * 4 + i;
#pragma unroll
        for (int jj = 0; jj < 4; ++jj) {
            int n = n0 + tx * 4 + jj;
            d_V[m*H + n] = tanhf(acc[i][jj] + d_attpre[b*H + n]);
        }
    }
}

// ---------------- K2b: att[m] = V[m] . W2 + b2 ----------------
__global__ __launch_bounds__(256) void att_dot_kernel(
    const float* __restrict__ W2, const float* __restrict__ b2)
{
    const int row  = blockIdx.x * 8 + (threadIdx.x >> 5);
    const int lane = threadIdx.x & 31;
    float s = 0.f;
#pragma unroll
    for (int i = 0; i < 8; ++i) {
        int jj = lane + i * 32;
        s += d_V[row*H + jj] * W2[jj];
    }
#pragma unroll
    for (int off = 16; off; off >>= 1) s += __shfl_xor_sync(0xffffffffu, s, off);
    if (lane == 0) d_att[row] = s + b2[0];
}

// ---------------- K4: softmax over T per batch (unmasked, like reference) ----------------
__global__ __launch_bounds__(256) void softmax_kernel()
{
    const int b = blockIdx.x, tid = threadIdx.x;
    __shared__ float sd[256];
    float x0 = d_att[b*T + tid];
    float x1 = d_att[b*T + 256 + tid];
    sd[tid] = fmaxf(x0, x1);
    __syncthreads();
    for (int s = 128; s; s >>= 1) {
        if (tid < s) sd[tid] = fmaxf(sd[tid], sd[tid + s]);
        __syncthreads();
    }
    const float M = sd[0];
    __syncthreads();
    float e0 = expf(x0 - M), e1 = expf(x1 - M);
    sd[tid] = e0 + e1;
    __syncthreads();
    for (int s = 128; s; s >>= 1) {
        if (tid < s) sd[tid] += sd[tid + s];
        __syncthreads();
    }
    const float inv = 1.0f / sd[0];
    d_g[b*T + tid]       = e0 * inv;
    d_g[b*T + 256 + tid] = e1 * inv;
}

// ---------------- K3: XRH GEMM (M=32768, K=256, N=512 = [Wr|Wh]) + bias ----------------
__global__ __launch_bounds__(256) void gemm_xrh_kernel(
    const float* __restrict__ fact, const float* __restrict__ Wr,
    const float* __restrict__ Wh,   const float* __restrict__ br,
    const float* __restrict__ bh)
{
    __shared__ float As[16][64];
    __shared__ float Bs[16][64];
    const int tid = threadIdx.x;
    const int m0 = blockIdx.x * 64;
    const int n0 = blockIdx.y * 64;
    const int tx = tid & 15, ty = tid >> 4;
    const int arow = tid >> 2, akq = (tid & 3) * 4;
    const int bkr = tid >> 4,  bjc = (tid & 15) * 4;

    const bool isR = (n0 < H);
    const float* __restrict__ W    = isR ? Wr : Wh;
    const float* __restrict__ bias = isR ? br : bh;
    const int nb = isR ? n0 : n0 - H;

    float acc[4][4] = {};
    for (int k0 = 0; k0 < H; k0 += 16) {
        float4 f4 = *(const float4*)(fact + (m0 + arow)*H + k0 + akq);
        As[akq + 0][arow] = f4.x;
        As[akq + 1][arow] = f4.y;
        As[akq + 2][arow] = f4.z;
        As[akq + 3][arow] = f4.w;
        *(float4*)&Bs[bkr][bjc] = *(const float4*)(W + (k0 + bkr)*H + nb + bjc);
        __syncthreads();
#pragma unroll
        for (int k = 0; k < 16; ++k) {
            float4 a  = *(const float4*)&As[k][ty * 4];
            float4 bb = *(const float4*)&Bs[k][tx * 4];
            acc[0][0] += a.x*bb.x; acc[0][1] += a.x*bb.y; acc[0][2] += a.x*bb.z; acc[0][3] += a.x*bb.w;
            acc[1][0] += a.y*bb.x; acc[1][1] += a.y*bb.y; acc[1][2] += a.y*bb.z; acc[1][3] += a.y*bb.w;
            acc[2][0] += a.z*bb.x; acc[2][1] += a.z*bb.y; acc[2][2] += a.z*bb.z; acc[2][3] += a.z*bb.w;
            acc[3][0] += a.w*bb.x; acc[3][1] += a.w*bb.y; acc[3][2] += a.w*bb.z; acc[3][3] += a.w*bb.w;
        }
        __syncthreads();
    }
#pragma unroll
    for (int i = 0; i < 4; ++i) {
        int m = m0 + ty * 4 + i;
#pragma unroll
        for (int jj = 0; jj < 4; ++jj) {
            int n = n0 + tx * 4 + jj;            // global col in [0,512)
            d_xrh[(size_t)m * (2*H) + n] = acc[i][jj] + bias[nb + tx*4 + jj];
        }
    }
}

// ---------------- K5: GRU recurrence, fused output dots ----------------
// One block per batch; thread j owns output column j. Ur/Uh stream from L2.
__global__ __launch_bounds__(256) void recurrence_kernel(
    const float* __restrict__ Ur, const float* __restrict__ Uh,
    const int* __restrict__ input_len,
    const float* __restrict__ Ws, const float* __restrict__ bs,
    const float* __restrict__ We, const float* __restrict__ be,
    float* __restrict__ out)
{
    const int b = blockIdx.x;
    const int j = threadIdx.x;
    __shared__ float h[H];
    __shared__ float rh[H];
    __shared__ float redS[8], redE[8];

    h[j] = 0.0f;
    const float ws2 = Ws[H + j];
    const float we2 = We[H + j];
    const int   len = input_len[b];
    const float msb = d_ms[b] + bs[0];
    const float meb = d_me[b] + be[0];
    const float* __restrict__ xb = d_xrh + (size_t)b * T * (2*H);
    __syncthreads();

    for (int t = 0; t < T; ++t) {
        const bool  valid = (t < len);
        const float gt = d_g[b*T + t];
        const float* __restrict__ x = xb + t * (2*H);

        // r = sigmoid(x@Wr + h@Ur + br)   (xr already contains br)
        float acc = x[j];
#pragma unroll 8
        for (int k = 0; k < H; ++k) acc += h[k] * Ur[k*H + j];
        const float r = 1.0f / (1.0f + expf(-acc));
        rh[j] = r * h[j];
        __syncthreads();

        // hc = tanh(x@Wh + (r*h)@Uh + bh)  (xh already contains bh)
        float acch = x[H + j];
#pragma unroll 8
        for (int k = 0; k < H; ++k) acch += rh[k] * Uh[k*H + j];
        const float hc = tanhf(acch);

        const float hj = h[j];
        const float hn = valid ? (gt * hc + (1.0f - gt) * hj) : hj;
        const float e  = valid ? hn : 0.0f;

        // fused output dots: e.Ws2, e.We2
        float ps = e * ws2, pe = e * we2;
#pragma unroll
        for (int off = 16; off; off >>= 1) {
            ps += __shfl_xor_sync(0xffffffffu, ps, off);
            pe += __shfl_xor_sync(0xffffffffu, pe, off);
        }
        if ((j & 31) == 0) { redS[j >> 5] = ps; redE[j >> 5] = pe; }
        __syncthreads();
        if (j == 0) {
            float s = 0.f, se = 0.f;
#pragma unroll
            for (int w = 0; w < 8; ++w) { s += redS[w]; se += redE[w]; }
            out[b*T + t]         = tanhf(msb + s);   // out_s
            out[B*T + b*T + t]   = tanhf(meb + se);  // out_e
        }
        h[j] = hn;              // safe: all reads of old h finished before first sync
        __syncthreads();
    }
}

// ---------------- entry point ----------------
extern "C" void kernel_launch(void* const* d_in, const int* in_sizes, int n_in,
                              void* d_out, int out_size)
{
    const float* qv   = (const float*)d_in[0];
    const float* fact = (const float*)d_in[1];
    const int*   ilen = (const int*)  d_in[2];
    const float* W1   = (const float*)d_in[3];
    const float* b1   = (const float*)d_in[4];
    const float* W2   = (const float*)d_in[5];
    const float* b2   = (const float*)d_in[6];
    const float* Wr   = (const float*)d_in[7];
    const float* Ur   = (const float*)d_in[8];
    const float* br   = (const float*)d_in[9];
    const float* Wh   = (const float*)d_in[10];
    const float* Uh   = (const float*)d_in[11];
    const float* bh   = (const float*)d_in[12];
    const float* Ws   = (const float*)d_in[13];
    const float* bs   = (const float*)d_in[14];
    const float* We   = (const float*)d_in[15];
    const float* be   = (const float*)d_in[16];
    float* out = (float*)d_out;

    prep_w_kernel<<<256, 256>>>(W1);
    prep_batch_kernel<<<64, 256>>>(qv, W1, b1, Ws, We);
    gemm_xrh_kernel<<<dim3(512, 8), 256>>>(fact, Wr, Wh, br, bh);
    gemm_att_kernel<<<dim3(512, 4), 256>>>(fact, qv, W1);
    att_dot_kernel<<<4096, 256>>>(W2, b2);
    softmax_kernel<<<64, 256>>>();
    recurrence_kernel<<<64, 256>>>(Ur, Uh, ilen, Ws, bs, We, be, out);
}

// round 8
// speedup vs baseline: 4.1599x; 4.1599x over previous
#include <cuda_runtime.h>
#include <cuda_fp16.h>
#include <math.h>

#define H 256
#define T 512
#define B 64
#define M_TOT (B*T)   // 32768

// ---------------- scratch (static device globals; no allocation) ----------------
__device__ float d_Wfq[H*H];            // W1[3H:4H] + W1[4H:5H]
__device__ float d_Wabs[H*H];           // W1[5H:6H] + W1[6H:7H]
__device__ float d_attpre[B*H];         // q@(W1[H:2H]+W1[2H:3H]) + b1
__device__ float d_ms[B];               // q . Ws[0:H]
__device__ float d_me[B];               // q . We[0:H]
__device__ float d_V[M_TOT*H];          // tanh(feats@W1 + b1)
__device__ float d_att[M_TOT];          // logits
__device__ float d_g[M_TOT];            // softmax gates
__device__ float d_xrh[(size_t)M_TOT*2*H]; // [m][0:256]=x@Wr+br, [256:512]=x@Wh+bh
__device__ __half d_Ur16[H*H];          // fp16 copy of Ur  [k][j]
__device__ __half d_Uh16[H*H];          // fp16 copy of Uh  [k][j]

// ---------------- K0: combine W1 slices ----------------
__global__ __launch_bounds__(256) void prep_w_kernel(const float* __restrict__ W1)
{
    int i = blockIdx.x * 256 + threadIdx.x;           // 65536 total
    d_Wfq[i]  = W1[196608 + i] + W1[262144 + i];      // rows [3H,4H) + [4H,5H)
    d_Wabs[i] = W1[327680 + i] + W1[393216 + i];      // rows [5H,6H) + [6H,7H)
}

// ---------------- K0b: fp16 conversion of Ur/Uh ----------------
__global__ __launch_bounds__(256) void prep_u16_kernel(
    const float* __restrict__ Ur, const float* __restrict__ Uh)
{
    int i = blockIdx.x * 256 + threadIdx.x;           // 65536 total
    d_Ur16[i] = __float2half(Ur[i]);
    d_Uh16[i] = __float2half(Uh[i]);
}

// ---------------- K1: per-batch precompute ----------------
__global__ __launch_bounds__(256) void prep_batch_kernel(
    const float* __restrict__ qv, const float* __restrict__ W1,
    const float* __restrict__ b1, const float* __restrict__ Ws,
    const float* __restrict__ We)
{
    const int b = blockIdx.x, j = threadIdx.x;
    __shared__ float qs[H];
    __shared__ float redS[8], redE[8];
    qs[j] = qv[b*H + j];
    __syncthreads();

    float acc = 0.f;
#pragma unroll 8
    for (int k = 0; k < H; ++k)
        acc += qs[k] * (W1[(H + k)*H + j] + W1[(2*H + k)*H + j]);
    d_attpre[b*H + j] = acc + b1[j];

    float ps = qs[j] * Ws[j];
    float pe = qs[j] * We[j];
#pragma unroll
    for (int off = 16; off; off >>= 1) {
        ps += __shfl_xor_sync(0xffffffffu, ps, off);
        pe += __shfl_xor_sync(0xffffffffu, pe, off);
    }
    if ((j & 31) == 0) { redS[j >> 5] = ps; redE[j >> 5] = pe; }
    __syncthreads();
    if (j == 0) {
        float s = 0.f, se = 0.f;
#pragma unroll
        for (int w = 0; w < 8; ++w) { s += redS[w]; se += redE[w]; }
        d_ms[b] = s;
        d_me[b] = se;
    }
}

// ---------------- K2a: attention GEMM (M=32768, K=768 virtual, N=256) ----------------
__global__ __launch_bounds__(256) void gemm_att_kernel(
    const float* __restrict__ fact, const float* __restrict__ qv,
    const float* __restrict__ W1)
{
    __shared__ float As[16][64];
    __shared__ float Bs[16][64];
    const int tid = threadIdx.x;
    const int m0 = blockIdx.x * 64;        // 64 consecutive rows: same batch (512/64=8)
    const int n0 = blockIdx.y * 64;
    const int b  = m0 >> 9;
    const int tx = tid & 15, ty = tid >> 4;
    const int arow = tid >> 2, akq = (tid & 3) * 4;
    const int bkr = tid >> 4,  bjc = (tid & 15) * 4;

    float acc[4][4] = {};

    for (int sel = 0; sel < 3; ++sel) {
        const float* __restrict__ W = (sel == 0) ? W1 : (sel == 1) ? d_Wfq : d_Wabs;
        for (int kp0 = 0; kp0 < H; kp0 += 16) {
            float4 f4 = *(const float4*)(fact + (m0 + arow)*H + kp0 + akq);
            float4 q4 = *(const float4*)(qv + b*H + kp0 + akq);
            float4 v4;
            if (sel == 0)      v4 = f4;
            else if (sel == 1) { v4.x = f4.x*q4.x; v4.y = f4.y*q4.y;
                                 v4.z = f4.z*q4.z; v4.w = f4.w*q4.w; }
            else               { v4.x = fabsf(f4.x - q4.x); v4.y = fabsf(f4.y - q4.y);
                                 v4.z = fabsf(f4.z - q4.z); v4.w = fabsf(f4.w - q4.w); }
            As[akq + 0][arow] = v4.x;
            As[akq + 1][arow] = v4.y;
            As[akq + 2][arow] = v4.z;
            As[akq + 3][arow] = v4.w;
            *(float4*)&Bs[bkr][bjc] = *(const float4*)(W + (kp0 + bkr)*H + n0 + bjc);
            __syncthreads();
#pragma unroll
            for (int k = 0; k < 16; ++k) {
                float4 a  = *(const float4*)&As[k][ty * 4];
                float4 bb = *(const float4*)&Bs[k][tx * 4];
                acc[0][0] += a.x*bb.x; acc[0][1] += a.x*bb.y; acc[0][2] += a.x*bb.z; acc[0][3] += a.x*bb.w;
                acc[1][0] += a.y*bb.x; acc[1][1] += a.y*bb.y; acc[1][2] += a.y*bb.z; acc[1][3] += a.y*bb.w;
                acc[2][0] += a.z*bb.x; acc[2][1] += a.z*bb.y; acc[2][2] += a.z*bb.z; acc[2][3] += a.z*bb.w;
                acc[3][0] += a.w*bb.x; acc[3][1] += a.w*bb.y; acc[3][2] += a.w*bb.z; acc[3][3] += a.w*bb.w;
            }
            __syncthreads();
        }
    }
#pragma unroll
    for (int i = 0; i < 4; ++i) {
        int m = m0 + ty * 4 + i;
#pragma unroll
        for (int jj = 0; jj < 4; ++jj) {
            int n = n0 + tx * 4 + jj;
            d_V[m*H + n] = tanhf(acc[i][jj] + d_attpre[b*H + n]);
        }
    }
}

// ---------------- K2b: att[m] = V[m] . W2 + b2 ----------------
__global__ __launch_bounds__(256) void att_dot_kernel(
    const float* __restrict__ W2, const float* __restrict__ b2)
{
    const int row  = blockIdx.x * 8 + (threadIdx.x >> 5);
    const int lane = threadIdx.x & 31;
    float s = 0.f;
#pragma unroll
    for (int i = 0; i < 8; ++i) {
        int jj = lane + i * 32;
        s += d_V[row*H + jj] * W2[jj];
    }
#pragma unroll
    for (int off = 16; off; off >>= 1) s += __shfl_xor_sync(0xffffffffu, s, off);
    if (lane == 0) d_att[row] = s + b2[0];
}

// ---------------- K4: softmax over T per batch ----------------
__global__ __launch_bounds__(256) void softmax_kernel()
{
    const int b = blockIdx.x, tid = threadIdx.x;
    __shared__ float sd[256];
    float x0 = d_att[b*T + tid];
    float x1 = d_att[b*T + 256 + tid];
    sd[tid] = fmaxf(x0, x1);
    __syncthreads();
    for (int s = 128; s; s >>= 1) {
        if (tid < s) sd[tid] = fmaxf(sd[tid], sd[tid + s]);
        __syncthreads();
    }
    const float M = sd[0];
    __syncthreads();
    float e0 = expf(x0 - M), e1 = expf(x1 - M);
    sd[tid] = e0 + e1;
    __syncthreads();
    for (int s = 128; s; s >>= 1) {
        if (tid < s) sd[tid] += sd[tid + s];
        __syncthreads();
    }
    const float inv = 1.0f / sd[0];
    d_g[b*T + tid]       = e0 * inv;
    d_g[b*T + 256 + tid] = e1 * inv;
}

// ---------------- K3: XRH GEMM (M=32768, K=256, N=512 = [Wr|Wh]) + bias ----------------
__global__ __launch_bounds__(256) void gemm_xrh_kernel(
    const float* __restrict__ fact, const float* __restrict__ Wr,
    const float* __restrict__ Wh,   const float* __restrict__ br,
    const float* __restrict__ bh)
{
    __shared__ float As[16][64];
    __shared__ float Bs[16][64];
    const int tid = threadIdx.x;
    const int m0 = blockIdx.x * 64;
    const int n0 = blockIdx.y * 64;
    const int tx = tid & 15, ty = tid >> 4;
    const int arow = tid >> 2, akq = (tid & 3) * 4;
    const int bkr = tid >> 4,  bjc = (tid & 15) * 4;

    const bool isR = (n0 < H);
    const float* __restrict__ W    = isR ? Wr : Wh;
    const float* __restrict__ bias = isR ? br : bh;
    const int nb = isR ? n0 : n0 - H;

    float acc[4][4] = {};
    for (int k0 = 0; k0 < H; k0 += 16) {
        float4 f4 = *(const float4*)(fact + (m0 + arow)*H + k0 + akq);
        As[akq + 0][arow] = f4.x;
        As[akq + 1][arow] = f4.y;
        As[akq + 2][arow] = f4.z;
        As[akq + 3][arow] = f4.w;
        *(float4*)&Bs[bkr][bjc] = *(const float4*)(W + (k0 + bkr)*H + nb + bjc);
        __syncthreads();
#pragma unroll
        for (int k = 0; k < 16; ++k) {
            float4 a  = *(const float4*)&As[k][ty * 4];
            float4 bb = *(const float4*)&Bs[k][tx * 4];
            acc[0][0] += a.x*bb.x; acc[0][1] += a.x*bb.y; acc[0][2] += a.x*bb.z; acc[0][3] += a.x*bb.w;
            acc[1][0] += a.y*bb.x; acc[1][1] += a.y*bb.y; acc[1][2] += a.y*bb.z; acc[1][3] += a.y*bb.w;
            acc[2][0] += a.z*bb.x; acc[2][1] += a.z*bb.y; acc[2][2] += a.z*bb.z; acc[2][3] += a.z*bb.w;
            acc[3][0] += a.w*bb.x; acc[3][1] += a.w*bb.y; acc[3][2] += a.w*bb.z; acc[3][3] += a.w*bb.w;
        }
        __syncthreads();
    }
#pragma unroll
    for (int i = 0; i < 4; ++i) {
        int m = m0 + ty * 4 + i;
#pragma unroll
        for (int jj = 0; jj < 4; ++jj) {
            int n = n0 + tx * 4 + jj;
            d_xrh[(size_t)m * (2*H) + n] = acc[i][jj] + bias[nb + tx*4 + jj];
        }
    }
}

// ---------------- K5: GRU recurrence (fp16 weights, vectorized, k-split) ----------------
// One block per batch, 512 threads = 16 warps.
// Warp kg (0..15) owns k-slice [kg*16, kg*16+16); lane jl owns 8 consecutive
// columns j0 = jl*8. Per k: one LDG.128 = 8 fp16 weights, 8 fp32 FMAs.
// Partials reduced through smem red[16][256]; per-column ops done by tid<256.
__global__ __launch_bounds__(512) void recurrence_kernel(
    const int* __restrict__ input_len,
    const float* __restrict__ Ws, const float* __restrict__ bs,
    const float* __restrict__ We, const float* __restrict__ be,
    float* __restrict__ out)
{
    const int b   = blockIdx.x;
    const int tid = threadIdx.x;
    const int kg  = tid >> 5;        // warp id = k-group
    const int jl  = tid & 31;
    const int j0  = jl * 8;
    const int k0  = kg * 16;

    __shared__ float h_s[H];
    __shared__ float rh_s[H];
    __shared__ float red[16][H];
    __shared__ float redS[8], redE[8];

    if (tid < H) h_s[tid] = 0.f;
    float ws2 = 0.f, we2 = 0.f, hj = 0.f;
    if (tid < H) { ws2 = Ws[H + tid]; we2 = We[H + tid]; }
    const int   len = input_len[b];
    const float msb = d_ms[b] + bs[0];
    const float meb = d_me[b] + be[0];
    const float* __restrict__ xb = d_xrh + (size_t)b * T * (2*H);
    __syncthreads();

    for (int t = 0; t < T; ++t) {
        // ---- phase 1: partial of h @ Ur for this warp's k-slice
        {
            float acc[8] = {};
            const __half* __restrict__ Wp = d_Ur16 + k0 * H + j0;
#pragma unroll
            for (int kk = 0; kk < 16; ++kk) {
                uint4 w = *(const uint4*)(Wp + kk * H);
                const float hk = h_s[k0 + kk];
                float2 f0 = __half22float2(*(const __half2*)&w.x);
                float2 f1 = __half22float2(*(const __half2*)&w.y);
                float2 f2 = __half22float2(*(const __half2*)&w.z);
                float2 f3 = __half22float2(*(const __half2*)&w.w);
                acc[0] = fmaf(hk, f0.x, acc[0]); acc[1] = fmaf(hk, f0.y, acc[1]);
                acc[2] = fmaf(hk, f1.x, acc[2]); acc[3] = fmaf(hk, f1.y, acc[3]);
                acc[4] = fmaf(hk, f2.x, acc[4]); acc[5] = fmaf(hk, f2.y, acc[5]);
                acc[6] = fmaf(hk, f3.x, acc[6]); acc[7] = fmaf(hk, f3.y, acc[7]);
            }
            *(float4*)&red[kg][j0]     = make_float4(acc[0], acc[1], acc[2], acc[3]);
            *(float4*)&red[kg][j0 + 4] = make_float4(acc[4], acc[5], acc[6], acc[7]);
        }
        __syncthreads();

        // ---- phase 2: r = sigmoid(xr + sum), rh = r*h   (tid<256: column tid)
        if (tid < H) {
            float s = xb[t * (2*H) + tid];
#pragma unroll
            for (int g = 0; g < 16; ++g) s += red[g][tid];
            const float r = 1.0f / (1.0f + expf(-s));
            hj = h_s[tid];
            rh_s[tid] = r * hj;
        }
        __syncthreads();

        // ---- phase 3: partial of rh @ Uh
        {
            float acc[8] = {};
            const __half* __restrict__ Wp = d_Uh16 + k0 * H + j0;
#pragma unroll
            for (int kk = 0; kk < 16; ++kk) {
                uint4 w = *(const uint4*)(Wp + kk * H);
                const float rk = rh_s[k0 + kk];
                float2 f0 = __half22float2(*(const __half2*)&w.x);
                float2 f1 = __half22float2(*(const __half2*)&w.y);
                float2 f2 = __half22float2(*(const __half2*)&w.z);
                float2 f3 = __half22float2(*(const __half2*)&w.w);
                acc[0] = fmaf(rk, f0.x, acc[0]); acc[1] = fmaf(rk, f0.y, acc[1]);
                acc[2] = fmaf(rk, f1.x, acc[2]); acc[3] = fmaf(rk, f1.y, acc[3]);
                acc[4] = fmaf(rk, f2.x, acc[4]); acc[5] = fmaf(rk, f2.y, acc[5]);
                acc[6] = fmaf(rk, f3.x, acc[6]); acc[7] = fmaf(rk, f3.y, acc[7]);
            }
            *(float4*)&red[kg][j0]     = make_float4(acc[0], acc[1], acc[2], acc[3]);
            *(float4*)&red[kg][j0 + 4] = make_float4(acc[4], acc[5], acc[6], acc[7]);
        }
        __syncthreads();

        // ---- phase 4: hc, hn, h update, fused output dots
        if (tid < H) {
            float s = xb[t * (2*H) + H + tid];
#pragma unroll
            for (int g = 0; g < 16; ++g) s += red[g][tid];
            const float hc = tanhf(s);
            const float gt = d_g[b*T + t];
            const bool  valid = (t < len);
            const float hn = valid ? fmaf(gt, hc - hj, hj) : hj;
            const float e  = valid ? hn : 0.f;
            h_s[tid] = hn;
            float ps = e * ws2, pe = e * we2;
#pragma unroll
            for (int off = 16; off; off >>= 1) {
                ps += __shfl_xor_sync(0xffffffffu, ps, off);
                pe += __shfl_xor_sync(0xffffffffu, pe, off);
            }
            if (jl == 0) { redS[kg] = ps; redE[kg] = pe; }   // kg in [0,8)
        }
        __syncthreads();

        // thread 0 finishes outputs while everyone else starts next step
        // (redS/redE not rewritten until after 3 more barriers)
        if (tid == 0) {
            float s = 0.f, se = 0.f;
#pragma unroll
            for (int w = 0; w < 8; ++w) { s += redS[w]; se += redE[w]; }
            out[b*T + t]       = tanhf(msb + s);   // out_s
            out[B*T + b*T + t] = tanhf(meb + se);  // out_e
        }
    }
}

// ---------------- entry point ----------------
extern "C" void kernel_launch(void* const* d_in, const int* in_sizes, int n_in,
                              void* d_out, int out_size)
{
    const float* qv   = (const float*)d_in[0];
    const float* fact = (const float*)d_in[1];
    const int*   ilen = (const int*)  d_in[2];
    const float* W1   = (const float*)d_in[3];
    const float* b1   = (const float*)d_in[4];
    const float* W2   = (const float*)d_in[5];
    const float* b2   = (const float*)d_in[6];
    const float* Wr   = (const float*)d_in[7];
    const float* Ur   = (const float*)d_in[8];
    const float* br   = (const float*)d_in[9];
    const float* Wh   = (const float*)d_in[10];
    const float* Uh   = (const float*)d_in[11];
    const float* bh   = (const float*)d_in[12];
    const float* Ws   = (const float*)d_in[13];
    const float* bs   = (const float*)d_in[14];
    const float* We   = (const float*)d_in[15];
    const float* be   = (const float*)d_in[16];
    float* out = (float*)d_out;

    prep_w_kernel<<<256, 256>>>(W1);
    prep_u16_kernel<<<256, 256>>>(Ur, Uh);
    prep_batch_kernel<<<64, 256>>>(qv, W1, b1, Ws, We);
    gemm_xrh_kernel<<<dim3(512, 8), 256>>>(fact, Wr, Wh, br, bh);
    gemm_att_kernel<<<dim3(512, 4), 256>>>(fact, qv, W1);
    att_dot_kernel<<<4096, 256>>>(W2, b2);
    softmax_kernel<<<64, 256>>>();
    recurrence_kernel<<<64, 512>>>(ilen, Ws, bs, We, be, out);
}